// round 1
// baseline (speedup 1.0000x reference)
#include <cuda_runtime.h>
#include <cuda_fp16.h>
#include <cstdint>

#define TT 4096
#define DD 1024
#define FF 2048
#define EE 8

// ---------------- scratch (no allocations allowed) ----------------
__device__ __half g_x16[TT * DD];          // x in fp16
__device__ __half g_wup[EE * FF * DD];     // W_up fp16
__device__ __half g_wga[EE * FF * DD];     // W_gate fp16
__device__ __half g_wdn[EE * DD * FF];     // W_down fp16
__device__ __half g_h[TT * FF];            // h = up * silu(gate), reused per expert
__device__ float  g_scale[TT * EE];        // routing scale per (token, expert)

// ---------------- small helpers ----------------
__device__ __forceinline__ uint32_t smem_u32(const void* p) {
    return (uint32_t)__cvta_generic_to_shared(p);
}
__device__ __forceinline__ void cp16(uint32_t s, const void* g) {
    asm volatile("cp.async.cg.shared.global [%0], [%1], 16;\n" :: "r"(s), "l"(g));
}
__device__ __forceinline__ void cp_commit() { asm volatile("cp.async.commit_group;\n"); }
template <int N>
__device__ __forceinline__ void cp_wait() { asm volatile("cp.async.wait_group %0;\n" :: "n"(N)); }

__device__ __forceinline__ void ldm4(uint32_t& r0, uint32_t& r1, uint32_t& r2, uint32_t& r3,
                                     uint32_t addr) {
    asm volatile("ldmatrix.sync.aligned.m8n8.x4.shared.b16 {%0,%1,%2,%3}, [%4];\n"
                 : "=r"(r0), "=r"(r1), "=r"(r2), "=r"(r3) : "r"(addr));
}
__device__ __forceinline__ void mma16816(float& d0, float& d1, float& d2, float& d3,
                                         uint32_t a0, uint32_t a1, uint32_t a2, uint32_t a3,
                                         uint32_t b0, uint32_t b1) {
    asm volatile("mma.sync.aligned.m16n8k16.row.col.f32.f16.f16.f32 "
                 "{%0,%1,%2,%3}, {%4,%5,%6,%7}, {%8,%9}, {%0,%1,%2,%3};\n"
                 : "+f"(d0), "+f"(d1), "+f"(d2), "+f"(d3)
                 : "r"(a0), "r"(a1), "r"(a2), "r"(a3), "r"(b0), "r"(b1));
}
__device__ __forceinline__ float silu_fast(float v) {
    return __fdividef(v, 1.f + __expf(-v));
}

// ---------------- fp32 -> fp16 conversion ----------------
__global__ void cvt_kernel(const float* __restrict__ src, int which, int n4) {
    int i = blockIdx.x * blockDim.x + threadIdx.x;
    if (i >= n4) return;
    __half* dst = (which == 0) ? g_x16 : (which == 1) ? g_wup : (which == 2) ? g_wga : g_wdn;
    float4 v = reinterpret_cast<const float4*>(src)[i];
    __half2 lo = __floats2half2_rn(v.x, v.y);
    __half2 hi = __floats2half2_rn(v.z, v.w);
    uint2 o;
    o.x = *reinterpret_cast<uint32_t*>(&lo);
    o.y = *reinterpret_cast<uint32_t*>(&hi);
    reinterpret_cast<uint2*>(dst)[i] = o;
}

// ---------------- probe: logits, threshold, scale (exact fp32) ----------------
__global__ void probe_kernel(const float* __restrict__ x, const float* __restrict__ Wp,
                             const float* __restrict__ bp, const float* __restrict__ taub,
                             const float* __restrict__ gam, const float* __restrict__ wd) {
    int gw = blockIdx.x * (blockDim.x >> 5) + (threadIdx.x >> 5);
    int lane = threadIdx.x & 31;
    int t = gw >> 3;
    int e = gw & 7;
    if (t >= TT) return;
    const float4* xr = reinterpret_cast<const float4*>(x + (size_t)t * DD);
    const float4* wr = reinterpret_cast<const float4*>(Wp + (size_t)e * DD);
    float acc = 0.f;
#pragma unroll
    for (int j = 0; j < 8; j++) {
        float4 a = xr[lane + 32 * j];
        float4 b = wr[lane + 32 * j];
        acc += a.x * b.x + a.y * b.y + a.z * b.z + a.w * b.w;
    }
#pragma unroll
    for (int o = 16; o; o >>= 1) acc += __shfl_xor_sync(0xffffffffu, acc, o);
    if (lane == 0) {
        float logit = acc + bp[e];
        float z = wd[0] * 0.5f;                               // w_depth * depth_ratio
        float tau = taub[0] + gam[0] * (z / (1.f + expf(-z)));  // logit-space threshold
        float s = (logit > tau) ? (1.f / (1.f + expf(-logit))) : 0.f;
        g_scale[t * EE + e] = s;
    }
}

// ---------------- GEMM A: up/gate + SwiGLU fused, h -> fp16 ----------------
// Tile: BM=128, BN=64 (both weights), BK=32. 8 warps (4m x 2n), warp tile 32x32.
#define SA 40  // padded smem row stride in halves

__global__ __launch_bounds__(256) void gemm_ug_kernel(int e) {
    __shared__ alignas(16) __half sX[2][128 * SA];
    __shared__ alignas(16) __half sU[2][64 * SA];
    __shared__ alignas(16) __half sG[2][64 * SA];
    const int tid = threadIdx.x;
    const int lane = tid & 31, wid = tid >> 5;
    const int wm = wid >> 1, wn = wid & 1;
    const int t0 = blockIdx.y * 128;
    const int f0 = blockIdx.x * 64;
    const __half* Wu = g_wup + (size_t)e * FF * DD;
    const __half* Wg = g_wga + (size_t)e * FF * DD;
    const int lc = tid & 3;   // 16B chunk within row
    const int lr = tid >> 2;  // 0..63

    float accU[2][4][4], accG[2][4][4];
#pragma unroll
    for (int a = 0; a < 2; a++)
#pragma unroll
        for (int b = 0; b < 4; b++)
#pragma unroll
            for (int c = 0; c < 4; c++) { accU[a][b][c] = 0.f; accG[a][b][c] = 0.f; }

    auto load_stage = [&](int buf, int k0) {
#pragma unroll
        for (int h = 0; h < 2; h++) {
            int r = lr + h * 64;
            cp16(smem_u32(&sX[buf][r * SA + lc * 8]),
                 g_x16 + (size_t)(t0 + r) * DD + k0 + lc * 8);
        }
        cp16(smem_u32(&sU[buf][lr * SA + lc * 8]), Wu + (size_t)(f0 + lr) * DD + k0 + lc * 8);
        cp16(smem_u32(&sG[buf][lr * SA + lc * 8]), Wg + (size_t)(f0 + lr) * DD + k0 + lc * 8);
    };

    load_stage(0, 0);
    cp_commit();

    const int NK = DD / 32;
    for (int kt = 0; kt < NK; kt++) {
        int buf = kt & 1;
        if (kt + 1 < NK) {
            load_stage(buf ^ 1, (kt + 1) * 32);
            cp_commit();
            cp_wait<1>();
        } else {
            cp_wait<0>();
        }
        __syncthreads();
#pragma unroll
        for (int kk = 0; kk < 2; kk++) {
            uint32_t a[2][4];
#pragma unroll
            for (int mi = 0; mi < 2; mi++) {
                int row = wm * 32 + mi * 16 + (lane & 15);
                int col = kk * 16 + (lane >> 4) * 8;
                ldm4(a[mi][0], a[mi][1], a[mi][2], a[mi][3],
                     smem_u32(&sX[buf][row * SA + col]));
            }
            uint32_t bu[4][2], bg[4][2];
#pragma unroll
            for (int nq = 0; nq < 2; nq++) {
                int n = wn * 32 + nq * 16 + (lane & 7) + ((lane >> 4) << 3);
                int kcol = kk * 16 + ((lane >> 3) & 1) * 8;
                uint32_t r0, r1, r2, r3;
                ldm4(r0, r1, r2, r3, smem_u32(&sU[buf][n * SA + kcol]));
                bu[nq * 2][0] = r0; bu[nq * 2][1] = r1;
                bu[nq * 2 + 1][0] = r2; bu[nq * 2 + 1][1] = r3;
                ldm4(r0, r1, r2, r3, smem_u32(&sG[buf][n * SA + kcol]));
                bg[nq * 2][0] = r0; bg[nq * 2][1] = r1;
                bg[nq * 2 + 1][0] = r2; bg[nq * 2 + 1][1] = r3;
            }
#pragma unroll
            for (int mi = 0; mi < 2; mi++)
#pragma unroll
                for (int nj = 0; nj < 4; nj++) {
                    mma16816(accU[mi][nj][0], accU[mi][nj][1], accU[mi][nj][2], accU[mi][nj][3],
                             a[mi][0], a[mi][1], a[mi][2], a[mi][3], bu[nj][0], bu[nj][1]);
                    mma16816(accG[mi][nj][0], accG[mi][nj][1], accG[mi][nj][2], accG[mi][nj][3],
                             a[mi][0], a[mi][1], a[mi][2], a[mi][3], bg[nj][0], bg[nj][1]);
                }
        }
        __syncthreads();
    }

    // epilogue: h = up * silu(gate), fp16 store
    const int g = lane >> 2, tg = lane & 3;
#pragma unroll
    for (int mi = 0; mi < 2; mi++)
#pragma unroll
        for (int nj = 0; nj < 4; nj++) {
            int row0 = t0 + wm * 32 + mi * 16 + g;
            int col = f0 + wn * 32 + nj * 8 + tg * 2;
            float h0 = accU[mi][nj][0] * silu_fast(accG[mi][nj][0]);
            float h1 = accU[mi][nj][1] * silu_fast(accG[mi][nj][1]);
            float h2 = accU[mi][nj][2] * silu_fast(accG[mi][nj][2]);
            float h3 = accU[mi][nj][3] * silu_fast(accG[mi][nj][3]);
            *reinterpret_cast<__half2*>(g_h + (size_t)row0 * FF + col) = __floats2half2_rn(h0, h1);
            *reinterpret_cast<__half2*>(g_h + (size_t)(row0 + 8) * FF + col) = __floats2half2_rn(h2, h3);
        }
}

// ---------------- GEMM B: down + scale-accumulate into out ----------------
// Tile: BM=128, BN=64, BK=32, K=FF. 8 warps (4m x 2n), warp tile 32x32.
__global__ __launch_bounds__(256) void gemm_dn_kernel(int e, float* __restrict__ out) {
    __shared__ alignas(16) __half sH[2][128 * SA];
    __shared__ alignas(16) __half sW[2][64 * SA];
    const int tid = threadIdx.x;
    const int lane = tid & 31, wid = tid >> 5;
    const int wm = wid >> 1, wn = wid & 1;
    const int t0 = blockIdx.y * 128;
    const int d0c = blockIdx.x * 64;
    const __half* Wd = g_wdn + (size_t)e * DD * FF;
    const int lc = tid & 3;
    const int lr = tid >> 2;

    float acc[2][4][4];
#pragma unroll
    for (int a = 0; a < 2; a++)
#pragma unroll
        for (int b = 0; b < 4; b++)
#pragma unroll
            for (int c = 0; c < 4; c++) acc[a][b][c] = 0.f;

    auto load_stage = [&](int buf, int k0) {
#pragma unroll
        for (int h = 0; h < 2; h++) {
            int r = lr + h * 64;
            cp16(smem_u32(&sH[buf][r * SA + lc * 8]),
                 g_h + (size_t)(t0 + r) * FF + k0 + lc * 8);
        }
        cp16(smem_u32(&sW[buf][lr * SA + lc * 8]), Wd + (size_t)(d0c + lr) * FF + k0 + lc * 8);
    };

    load_stage(0, 0);
    cp_commit();

    const int NK = FF / 32;
    for (int kt = 0; kt < NK; kt++) {
        int buf = kt & 1;
        if (kt + 1 < NK) {
            load_stage(buf ^ 1, (kt + 1) * 32);
            cp_commit();
            cp_wait<1>();
        } else {
            cp_wait<0>();
        }
        __syncthreads();
#pragma unroll
        for (int kk = 0; kk < 2; kk++) {
            uint32_t a[2][4];
#pragma unroll
            for (int mi = 0; mi < 2; mi++) {
                int row = wm * 32 + mi * 16 + (lane & 15);
                int col = kk * 16 + (lane >> 4) * 8;
                ldm4(a[mi][0], a[mi][1], a[mi][2], a[mi][3],
                     smem_u32(&sH[buf][row * SA + col]));
            }
            uint32_t bw[4][2];
#pragma unroll
            for (int nq = 0; nq < 2; nq++) {
                int n = wn * 32 + nq * 16 + (lane & 7) + ((lane >> 4) << 3);
                int kcol = kk * 16 + ((lane >> 3) & 1) * 8;
                uint32_t r0, r1, r2, r3;
                ldm4(r0, r1, r2, r3, smem_u32(&sW[buf][n * SA + kcol]));
                bw[nq * 2][0] = r0; bw[nq * 2][1] = r1;
                bw[nq * 2 + 1][0] = r2; bw[nq * 2 + 1][1] = r3;
            }
#pragma unroll
            for (int mi = 0; mi < 2; mi++)
#pragma unroll
                for (int nj = 0; nj < 4; nj++)
                    mma16816(acc[mi][nj][0], acc[mi][nj][1], acc[mi][nj][2], acc[mi][nj][3],
                             a[mi][0], a[mi][1], a[mi][2], a[mi][3], bw[nj][0], bw[nj][1]);
        }
        __syncthreads();
    }

    // epilogue: out[t,d] (+)= scale[t,e] * down[t,d]
    const int g = lane >> 2, tg = lane & 3;
    const bool accumulate = (e != 0);
#pragma unroll
    for (int mi = 0; mi < 2; mi++) {
        int row0 = t0 + wm * 32 + mi * 16 + g;
        int row1 = row0 + 8;
        float s0 = g_scale[row0 * EE + e];
        float s1 = g_scale[row1 * EE + e];
#pragma unroll
        for (int nj = 0; nj < 4; nj++) {
            int col = d0c + wn * 32 + nj * 8 + tg * 2;
            float* p0 = out + (size_t)row0 * DD + col;
            float* p1 = out + (size_t)row1 * DD + col;
            if (accumulate) {
                if (s0 != 0.f) {
                    float2 v = *reinterpret_cast<float2*>(p0);
                    v.x += s0 * acc[mi][nj][0];
                    v.y += s0 * acc[mi][nj][1];
                    *reinterpret_cast<float2*>(p0) = v;
                }
                if (s1 != 0.f) {
                    float2 v = *reinterpret_cast<float2*>(p1);
                    v.x += s1 * acc[mi][nj][2];
                    v.y += s1 * acc[mi][nj][3];
                    *reinterpret_cast<float2*>(p1) = v;
                }
            } else {
                float2 v0 = make_float2(s0 * acc[mi][nj][0], s0 * acc[mi][nj][1]);
                float2 v1 = make_float2(s1 * acc[mi][nj][2], s1 * acc[mi][nj][3]);
                *reinterpret_cast<float2*>(p0) = v0;
                *reinterpret_cast<float2*>(p1) = v1;
            }
        }
    }
}

// ---------------- launch ----------------
extern "C" void kernel_launch(void* const* d_in, const int* in_sizes, int n_in,
                              void* d_out, int out_size) {
    const float* x    = (const float*)d_in[0];
    const float* Wp   = (const float*)d_in[1];
    const float* bp   = (const float*)d_in[2];
    const float* Wu   = (const float*)d_in[3];
    const float* Wg   = (const float*)d_in[4];
    const float* Wd   = (const float*)d_in[5];
    const float* taub = (const float*)d_in[6];
    const float* gam  = (const float*)d_in[7];
    const float* wdep = (const float*)d_in[8];
    float* out = (float*)d_out;

    cvt_kernel<<<(TT * DD / 4 + 255) / 256, 256>>>(x, 0, TT * DD / 4);
    cvt_kernel<<<(EE * FF * DD / 4 + 255) / 256, 256>>>(Wu, 1, EE * FF * DD / 4);
    cvt_kernel<<<(EE * FF * DD / 4 + 255) / 256, 256>>>(Wg, 2, EE * FF * DD / 4);
    cvt_kernel<<<(EE * DD * FF / 4 + 255) / 256, 256>>>(Wd, 3, EE * DD * FF / 4);
    probe_kernel<<<TT * EE / 8, 256>>>(x, Wp, bp, taub, gam, wdep);

    for (int e = 0; e < EE; e++) {
        gemm_ug_kernel<<<dim3(FF / 64, TT / 128), 256>>>(e);
        gemm_dn_kernel<<<dim3(DD / 64, TT / 128), 256>>>(e, out);
    }
}